// round 16
// baseline (speedup 1.0000x reference)
#include <cuda_runtime.h>
#include <math.h>

#define HCH   512
#define NST   32
#define LEN   4096
#define M2    8192
#define BSZ   8
#define FCNT  2049
#define PI_D  3.14159265358979323846
#define C707  0.70710678118654752440f
#define CS16  0.92387953251128675613f
#define SN16  0.38268343236508977172f
#define SMEMN (M2 + (M2/16)*4)    /* 10240 float2 data region (pad 4 per 16) */
#define TWN   1024                /* smem twiddle table entries */
#define SMEMB ((SMEMN + TWN) * 8) /* 90112 bytes */

__device__ float2 g_kf[HCH * FCNT];
__device__ float2 g_KF[HCH * M2];        // scrambled order, NATURAL per-thread runs of 16
__device__ float  g_xT[BSZ * HCH * LEN];
__device__ float  g_yT[BSZ * HCH * LEN];
__device__ float2 g_tw[M2 / 2];          // exp(-2pi i k/8192)

__device__ __forceinline__ int P(int i) { return i + ((i >> 4) << 2); }

union F2U { float2 f; unsigned long long u; };

__device__ __forceinline__ float2 cadd(float2 a, float2 b) {
    F2U ua, ub, uc; ua.f = a; ub.f = b;
    asm("add.rn.f32x2 %0, %1, %2;" : "=l"(uc.u) : "l"(ua.u), "l"(ub.u));
    return uc.f;
}
__device__ __forceinline__ float2 csub(float2 a, float2 b) {
    F2U ua, ub, uc; ua.f = a; ub.f = b;
    const unsigned long long NEG1 = 0xBF800000BF800000ULL;
    asm("fma.rn.f32x2 %0, %1, %2, %3;" : "=l"(uc.u)
        : "l"(ub.u), "l"(NEG1), "l"(ua.u));
    return uc.f;
}
__device__ __forceinline__ float2 cmulf(float2 a, float2 b) {
    return make_float2(a.x * b.x - a.y * b.y, a.x * b.y + a.y * b.x);
}

// forward 8-pt DIF network; slot r holds X[bitrev3(r)]
__device__ __forceinline__ void fft8f(float2 v[8]) {
    float2 a0=cadd(v[0],v[4]), a4=csub(v[0],v[4]);
    float2 a1=cadd(v[1],v[5]), a5=csub(v[1],v[5]);
    float2 a2=cadd(v[2],v[6]), a6=csub(v[2],v[6]);
    float2 a3=cadd(v[3],v[7]), a7=csub(v[3],v[7]);
    float2 t5 = make_float2(C707*(a5.x+a5.y),  C707*(a5.y-a5.x));   // *W8^1
    float2 t6 = make_float2(a6.y, -a6.x);                           // *W8^2
    float2 t7 = make_float2(C707*(a7.y-a7.x), -C707*(a7.x+a7.y));   // *W8^3
    float2 b0=cadd(a0,a2), b2=csub(a0,a2);
    float2 b1=cadd(a1,a3), b3=csub(a1,a3);
    float2 b4=cadd(a4,t6), b6=csub(a4,t6);
    float2 b5=cadd(t5,t7), b7=csub(t5,t7);
    float2 u3 = make_float2(b3.y, -b3.x);                           // *-i
    float2 u7 = make_float2(b7.y, -b7.x);
    v[0]=cadd(b0,b1); v[1]=csub(b0,b1);
    v[2]=cadd(b2,u3); v[3]=csub(b2,u3);
    v[4]=cadd(b4,b5); v[5]=csub(b4,b5);
    v[6]=cadd(b6,u7); v[7]=csub(b6,u7);
}

// exact mirror: input in fft8f slot order, output natural, unnormalized (x8)
__device__ __forceinline__ void ifft8(float2 v[8]) {
    float2 b0=cadd(v[0],v[1]), b1=csub(v[0],v[1]);
    float2 b2=cadd(v[2],v[3]), b3=csub(v[2],v[3]);
    float2 b4=cadd(v[4],v[5]), b5=csub(v[4],v[5]);
    float2 b6=cadd(v[6],v[7]), b7=csub(v[6],v[7]);
    b3 = make_float2(-b3.y, b3.x);   // *+i
    b7 = make_float2(-b7.y, b7.x);
    float2 a0=cadd(b0,b2), a2=csub(b0,b2);
    float2 a1=cadd(b1,b3), a3=csub(b1,b3);
    float2 a4=cadd(b4,b6), a6=csub(b4,b6);
    float2 a5=cadd(b5,b7), a7=csub(b5,b7);
    a5 = make_float2(C707*(a5.x-a5.y), C707*(a5.x+a5.y));   // *W8^-1
    a6 = make_float2(-a6.y, a6.x);                           // *+i
    a7 = make_float2(-C707*(a7.x+a7.y), C707*(a7.x-a7.y));  // *W8^-3
    v[0]=cadd(a0,a4); v[4]=csub(a0,a4);
    v[1]=cadd(a1,a5); v[5]=csub(a1,a5);
    v[2]=cadd(a2,a6); v[6]=csub(a2,a6);
    v[3]=cadd(a3,a7); v[7]=csub(a3,a7);
}

// 16-pt forward (DIT split even/odd); output slot s holds freq bitrev4(s)
__device__ __forceinline__ void fft16_fwd(float2 v[16]) {
    float2 g[8];
    #pragma unroll
    for (int r = 0; r < 8; r++) g[r] = v[2*r];
    fft8f(g);
    #pragma unroll
    for (int r = 0; r < 8; r++) v[2*r] = g[r];
    #pragma unroll
    for (int r = 0; r < 8; r++) g[r] = v[2*r+1];
    fft8f(g);
    { float2 x=g[1]; g[1]=make_float2( x.y, -x.x); }                              // W16^4
    { float2 x=g[2]; g[2]=make_float2(C707*(x.x+x.y),  C707*(x.y-x.x)); }         // W16^2
    { float2 x=g[3]; g[3]=make_float2(C707*(x.y-x.x), -C707*(x.x+x.y)); }         // W16^6
    { float2 x=g[4]; g[4]=make_float2(CS16*x.x+SN16*x.y,  CS16*x.y-SN16*x.x); }   // W16^1
    { float2 x=g[5]; g[5]=make_float2(CS16*x.y-SN16*x.x, -(CS16*x.x+SN16*x.y)); } // W16^5
    { float2 x=g[6]; g[6]=make_float2(SN16*x.x+CS16*x.y,  SN16*x.y-CS16*x.x); }   // W16^3
    { float2 x=g[7]; g[7]=make_float2(SN16*x.y-CS16*x.x, -(SN16*x.x+CS16*x.y)); } // W16^7
    #pragma unroll
    for (int r = 0; r < 8; r++) v[2*r+1] = g[r];
    #pragma unroll
    for (int r = 0; r < 8; r++) {
        float2 u = v[2*r], w = v[2*r+1];
        v[2*r] = cadd(u, w); v[2*r+1] = csub(u, w);
    }
}

// exact mirror of fft16_fwd, unnormalized (x16)
__device__ __forceinline__ void fft16_inv(float2 v[16]) {
    #pragma unroll
    for (int r = 0; r < 8; r++) {
        float2 u = v[2*r], w = v[2*r+1];
        v[2*r] = cadd(u, w); v[2*r+1] = csub(u, w);
    }
    float2 g[8];
    #pragma unroll
    for (int r = 0; r < 8; r++) g[r] = v[2*r];
    ifft8(g);
    #pragma unroll
    for (int r = 0; r < 8; r++) v[2*r] = g[r];
    #pragma unroll
    for (int r = 0; r < 8; r++) g[r] = v[2*r+1];
    { float2 x=g[1]; g[1]=make_float2(-x.y,  x.x); }
    { float2 x=g[2]; g[2]=make_float2(C707*(x.x-x.y),  C707*(x.x+x.y)); }
    { float2 x=g[3]; g[3]=make_float2(-C707*(x.x+x.y), C707*(x.x-x.y)); }
    { float2 x=g[4]; g[4]=make_float2(CS16*x.x-SN16*x.y,  CS16*x.y+SN16*x.x); }
    { float2 x=g[5]; g[5]=make_float2(-(SN16*x.x+CS16*x.y), CS16*x.x-SN16*x.y); }
    { float2 x=g[6]; g[6]=make_float2(SN16*x.x-CS16*x.y,  SN16*x.y+CS16*x.x); }
    { float2 x=g[7]; g[7]=make_float2(-(CS16*x.x+SN16*x.y), SN16*x.x-CS16*x.y); }
    ifft8(g);
    #pragma unroll
    for (int r = 0; r < 8; r++) v[2*r+1] = g[r];
}

// apply the 7 forward twiddles (slot order) given w1
__device__ __forceinline__ void twiddle_fwd(float2 v[8], float2 w1) {
    float2 w2 = cmulf(w1,w1), w3 = cmulf(w2,w1), w4 = cmulf(w2,w2);
    v[1]=cmulf(v[1],w4); v[2]=cmulf(v[2],w2); v[3]=cmulf(v[3],cmulf(w4,w2));
    v[4]=cmulf(v[4],w1); v[5]=cmulf(v[5],cmulf(w4,w1)); v[6]=cmulf(v[6],w3);
    v[7]=cmulf(v[7],cmulf(w4,w3));
}

// smem radix-8 DIF stage; NBF butterflies per thread (512 threads).
template<int L, int NBF>
__device__ __forceinline__ void stage8_dif(float2* a, const float2* tw) {
    const int half = L >> 3, tws = M2 / L, t = threadIdx.x;
    #pragma unroll
    for (int ii = 0; ii < NBF; ii++) {
        int i = t + ii * 512;
        int j = i & (half - 1);
        int p0 = ((i - j) << 3) + j;
        float2 v[8];
        #pragma unroll
        for (int r = 0; r < 8; r++) v[r] = a[P(p0 + r * half)];
        fft8f(v);
        twiddle_fwd(v, tw[j * tws]);
        #pragma unroll
        for (int r = 0; r < 8; r++) a[P(p0 + r * half)] = v[r];
    }
    __syncthreads();
}

// inverse mirror: conj twiddles first, then ifft8
template<int L, int NBF>
__device__ __forceinline__ void stage8_dit(float2* a, const float2* tw) {
    const int half = L >> 3, tws = M2 / L, t = threadIdx.x;
    #pragma unroll
    for (int ii = 0; ii < NBF; ii++) {
        int i = t + ii * 512;
        int j = i & (half - 1);
        int p0 = ((i - j) << 3) + j;
        float2 v[8];
        #pragma unroll
        for (int r = 0; r < 8; r++) v[r] = a[P(p0 + r * half)];
        float2 w1 = tw[j * tws]; w1.y = -w1.y;
        twiddle_fwd(v, w1);
        ifft8(v);
        #pragma unroll
        for (int r = 0; r < 8; r++) a[P(p0 + r * half)] = v[r];
    }
    __syncthreads();
}

// first 8192 DIF stage with upper half == 0, inputs from two real gmem series
__device__ __forceinline__ void stage1_fwd_gmem(float2* a, const float2* tw,
                                                const float* __restrict__ x0,
                                                const float* __restrict__ x1) {
    const int t = threadIdx.x;
    #pragma unroll
    for (int ii = 0; ii < 2; ii++) {
        int i = t + ii * 512;
        float2 v[8];
        #pragma unroll
        for (int r = 0; r < 4; r++) v[r] = make_float2(x0[i + r*1024], x1[i + r*1024]);
        #pragma unroll
        for (int r = 4; r < 8; r++) v[r] = make_float2(0.f, 0.f);
        fft8f(v);
        twiddle_fwd(v, tw[i]);
        #pragma unroll
        for (int r = 0; r < 8; r++) a[P(i + r * 1024)] = v[r];
    }
    __syncthreads();
}

// first 8192 DIF stage with upper half == 0, lower half already in smem (in place safe)
__device__ __forceinline__ void stage1_fwd_half(float2* a, const float2* tw) {
    const int t = threadIdx.x;
    #pragma unroll
    for (int ii = 0; ii < 2; ii++) {
        int i = t + ii * 512;
        float2 v[8];
        #pragma unroll
        for (int r = 0; r < 4; r++) v[r] = a[P(i + r*1024)];
        #pragma unroll
        for (int r = 4; r < 8; r++) v[r] = make_float2(0.f, 0.f);
        fft8f(v);
        twiddle_fwd(v, tw[i]);
        #pragma unroll
        for (int r = 0; r < 8; r++) a[P(i + r * 1024)] = v[r];
    }
    __syncthreads();
}

// last 8192 DIT stage fused with epilogue: only times < 4096 kept (D folded into K)
__device__ __forceinline__ void stageF_inv_gmem(float2* a, const float2* tw,
                                                float* __restrict__ y0,
                                                float* __restrict__ y1) {
    const int t = threadIdx.x;
    const float inv = 1.0f / (float)M2;
    #pragma unroll
    for (int ii = 0; ii < 2; ii++) {
        int i = t + ii * 512;
        float2 v[8];
        #pragma unroll
        for (int r = 0; r < 8; r++) v[r] = a[P(i + r * 1024)];
        float2 w1 = tw[i]; w1.y = -w1.y;
        twiddle_fwd(v, w1);
        ifft8(v);
        #pragma unroll
        for (int r = 0; r < 4; r++) {
            int p = i + r * 1024;
            y0[p] = v[r].x * inv;
            y1[p] = v[r].y * inv;
        }
    }
}

// middle of the 8192 transform; tail loaded as float4 with lane-rotated order
__device__ __forceinline__ void fwd8192_tail(float2* a, const float2* tw, float2 v[16]) {
    stage8_dif<1024,2>(a, tw);
    stage8_dif<128,2>(a, tw);
    const int t = threadIdx.x;
    const int lrot = (t >> 2) & 7;
    const float4* af = reinterpret_cast<const float4*>(a);
    const int base = 10 * t;            // float4 index of P(16t) = 20t float2s
    #pragma unroll
    for (int r2 = 0; r2 < 8; r2++) {
        int rr = (r2 + lrot) & 7;
        float4 q = af[base + rr];
        v[2*rr]   = make_float2(q.x, q.y);
        v[2*rr+1] = make_float2(q.z, q.w);
    }
    fft16_fwd(v);
}

__device__ __forceinline__ void inv8192_head(float2* a, const float2* tw, float2 v[16]) {
    fft16_inv(v);
    const int t = threadIdx.x;
    const int lrot = (t >> 2) & 7;
    float4* af = reinterpret_cast<float4*>(a);
    const int base = 10 * t;
    #pragma unroll
    for (int r2 = 0; r2 < 8; r2++) {
        int rr = (r2 + lrot) & 7;
        af[base + rr] = make_float4(v[2*rr].x, v[2*rr].y, v[2*rr+1].x, v[2*rr+1].y);
    }
    __syncthreads();
    stage8_dit<128,2>(a, tw);
    stage8_dit<1024,2>(a, tw);
}

// Cauchy accumulation over modes; PAIRED halves divisions (unsafe only at f=2048)
template<bool PAIRED>
__device__ __forceinline__ void cauchy_acc(const float2 s_v[4][NST], const float2* s_wd,
                                           float zy, float2 r[4]) {
    #pragma unroll 8
    for (int n = 0; n < NST; n++) {
        float2 wd = s_wd[n];
        float dx = -wd.x, d1y = zy - wd.y, d2y = zy + wd.y;
        float A = dx*dx + d1y*d1y;
        float B = dx*dx + d2y*d2y;
        float m1, m2;
        if (PAIRED) {
            float invp = 1.0f / (A * B);
            m1 = invp * B; m2 = invp * A;
        } else {
            m1 = 1.0f / A; m2 = 1.0f / B;
        }
        float i1x = dx*m1, i1y = -d1y*m1;
        float i2x = dx*m2, i2y = -d2y*m2;
        float sx = i1x + i2x, dxy = i1y - i2y;
        float sy = i1y + i2y, dxx = i1x - i2x;
        float2 v;
        v = s_v[0][n]; r[0].x += v.x*sx - v.y*dxy; r[0].y += v.x*sy + v.y*dxx;
        v = s_v[1][n]; r[1].x += v.x*sx - v.y*dxy; r[1].y += v.x*sy + v.y*dxx;
        v = s_v[2][n]; r[2].x += v.x*sx - v.y*dxy; r[2].y += v.x*sy + v.y*dxx;
        v = s_v[3][n]; r[3].x += v.x*sx - v.y*dxy; r[3].y += v.x*sy + v.y*dxx;
    }
}

// Cauchy + Woodbury (also fills the global twiddle table — one fewer launch)
__global__ void k_cauchy(const float* __restrict__ log_dt,
                         const float2* __restrict__ w,
                         const float2* __restrict__ Bm,
                         const float2* __restrict__ Cm) {
    const int h = blockIdx.x, t = threadIdx.x;  // 256 thr
    int gid = h * 256 + t;
    if (gid < M2 / 2) {
        double sd, cd;
        sincos(-2.0 * PI_D * (double)gid / (double)M2, &sd, &cd);
        g_tw[gid] = make_float2((float)cd, (float)sd);
    }

    __shared__ float2 s_v[4][NST];
    __shared__ float2 s_wd[NST];
    __shared__ float s_dt;
    float dt = expf(log_dt[h]);
    if (t == 0) s_dt = dt;
    if (t < NST) { float2 ww = w[t]; s_wd[t] = make_float2(ww.x*dt, ww.y*dt); }
    if (t < 4 * NST) {
        int ab = t >> 5, n = t & 31, ai = ab >> 1, b = ab & 1;
        float2 C  = Cm[(h*2 + ai)*NST + n];
        float2 Bv = Bm[(h*2 + b)*NST + n];
        s_v[ab][n] = make_float2(C.x*Bv.x + C.y*Bv.y, C.x*Bv.y - C.y*Bv.x);
    }
    __syncthreads();
    dt = s_dt;
    const float piL = (float)(PI_D / LEN);
    for (int f = t; f < FCNT; f += blockDim.x) {
        float s;
        if (f == 0)          s = 0.0f;
        else if (f <= 1024)  s = tanf((float)f * piL);
        else if (f == 2048)  s = 1.633123935319537e16f;
        else                 s = 1.0f / tanf((float)(2048 - f) * piL);
        float zy = 2.0f * s;
        float2 r[4] = {make_float2(0,0), make_float2(0,0),
                       make_float2(0,0), make_float2(0,0)};
        if (f == 2048) cauchy_acc<false>(s_v, s_wd, zy, r);
        else           cauchy_acc<true >(s_v, s_wd, zy, r);
        #pragma unroll
        for (int k = 0; k < 4; k++) { r[k].x *= dt; r[k].y *= dt; }
        float2 den = make_float2(1.0f + r[3].x, r[3].y);
        float dm = 1.0f / (den.x*den.x + den.y*den.y);
        float2 num = cmulf(r[1], r[2]);
        float2 q = make_float2((num.x*den.x + num.y*den.y)*dm,
                               (num.y*den.x - num.x*den.y)*dm);
        float2 kf = make_float2(r[0].x - q.x, r[0].y - q.y);
        g_kf[h*FCNT + f] = make_float2(kf.x - kf.y*s, kf.y + kf.x*s);
    }
}

// makeK: ifft4096 via conj-forward (radix-8), scatter, half-zero first stage,
// forward 8192, fold D, store KF in natural per-thread runs (float4).
__global__ __launch_bounds__(512, 2) void k_makeK(const float* __restrict__ D) {
    extern __shared__ float2 a[];
    float2* sw = a + SMEMN;
    const int h = blockIdx.x, t = threadIdx.x;

    for (int i = t; i < TWN; i += 512) sw[i] = g_tw[i];

    for (int f = t; f < FCNT; f += 512) {
        float2 vv = g_kf[h*FCNT + f];
        if (f == 0 || f == 2048) vv.y = 0.f;
        a[P(f)] = make_float2(vv.x, -vv.y);           // conj
        if (f > 0 && f < 2048) a[P(4096 - f)] = vv;
    }
    __syncthreads();

    stage8_dif<4096,1>(a, sw);
    stage8_dif<512,1>(a, sw);
    stage8_dif<64,1>(a, sw);
    float2 v8[8];
    #pragma unroll
    for (int r = 0; r < 8; r++) v8[r] = a[P(8*t + r)];
    fft8f(v8);
    __syncthreads();

    #pragma unroll
    for (int r = 0; r < 8; r++) {
        int p = 8*t + r;
        int m = __brev((unsigned)p) >> 20;   // bitrev12
        a[P(m)] = make_float2(v8[r].x * (1.0f / 4096.0f), 0.f);
    }
    __syncthreads();

    float2 v[16];
    stage1_fwd_half(a, sw);
    fwd8192_tail(a, sw, v);

    const float Dh = D[h];
    float4* KFf = reinterpret_cast<float4*>(g_KF + (size_t)h * M2);
    #pragma unroll
    for (int r2 = 0; r2 < 8; r2++)
        KFf[8*t + r2] = make_float4(v[2*r2].x + Dh, v[2*r2].y,
                                    v[2*r2+1].x + Dh, v[2*r2+1].y);
}

// transposes: float4 on both gmem sides, tile[32][36]
__global__ void k_transpose_x(const float* __restrict__ x) {
    __shared__ float tile[32][36];          // [h_local][t_local]
    const int b = blockIdx.z, h0 = blockIdx.x*32, t0 = blockIdx.y*32;
    const int tx = threadIdx.x;             // 0..7
    const int ty = threadIdx.y;             // 0..31
    float4 q = *reinterpret_cast<const float4*>(
        &x[((size_t)b*LEN + t0 + ty)*HCH + h0 + 4*tx]);
    tile[4*tx+0][ty] = q.x; tile[4*tx+1][ty] = q.y;
    tile[4*tx+2][ty] = q.z; tile[4*tx+3][ty] = q.w;
    __syncthreads();
    float4 o = *reinterpret_cast<const float4*>(&tile[ty][4*tx]);
    *reinterpret_cast<float4*>(
        &g_xT[((size_t)b*HCH + h0 + ty)*LEN + t0 + 4*tx]) = o;
}

__global__ void k_transpose_y(float* __restrict__ out) {
    __shared__ float tile[32][36];          // [t_local][h_local]
    const int b = blockIdx.z, t0 = blockIdx.x*32, h0 = blockIdx.y*32;
    const int tx = threadIdx.x;             // 0..7
    const int ty = threadIdx.y;             // 0..31
    float4 q = *reinterpret_cast<const float4*>(
        &g_yT[((size_t)b*HCH + h0 + ty)*LEN + t0 + 4*tx]);
    tile[4*tx+0][ty] = q.x; tile[4*tx+1][ty] = q.y;
    tile[4*tx+2][ty] = q.z; tile[4*tx+3][ty] = q.w;
    __syncthreads();
    float4 o = *reinterpret_cast<const float4*>(&tile[ty][4*tx]);
    *reinterpret_cast<float4*>(
        &out[((size_t)b*LEN + t0 + ty)*HCH + h0 + 4*tx]) = o;
}

__global__ __launch_bounds__(512, 2) void k_conv() {
    extern __shared__ float2 a[];
    float2* sw = a + SMEMN;
    const int c = blockIdx.x, h = c & (HCH - 1), q = c >> 9, t = threadIdx.x;
    const float* x0 = g_xT + ((size_t)(2*q)*HCH + h)*LEN;
    const float* x1 = g_xT + ((size_t)(2*q + 1)*HCH + h)*LEN;

    for (int i = t; i < TWN; i += 512) sw[i] = g_tw[i];
    __syncthreads();

    float2 v[16];
    stage1_fwd_gmem(a, sw, x0, x1);
    fwd8192_tail(a, sw, v);

    const float4* KFf = reinterpret_cast<const float4*>(g_KF + (size_t)h * M2);
    #pragma unroll
    for (int r2 = 0; r2 < 8; r2++) {
        float4 kq = KFf[8*t + r2];
        v[2*r2]   = cmulf(v[2*r2],   make_float2(kq.x, kq.y));
        v[2*r2+1] = cmulf(v[2*r2+1], make_float2(kq.z, kq.w));
    }

    inv8192_head(a, sw, v);
    stageF_inv_gmem(a, sw,
                    g_yT + ((size_t)(2*q)*HCH + h)*LEN,
                    g_yT + ((size_t)(2*q + 1)*HCH + h)*LEN);
}

extern "C" void kernel_launch(void* const* d_in, const int* in_sizes, int n_in,
                              void* d_out, int out_size) {
    const float*  x      = (const float*)d_in[0];
    const float*  log_dt = (const float*)d_in[1];
    const float2* w      = (const float2*)d_in[2];
    const float2* Bm     = (const float2*)d_in[3];
    const float2* Cm     = (const float2*)d_in[4];
    const float*  D      = (const float*)d_in[5];
    float* out = (float*)d_out;
    (void)in_sizes; (void)n_in; (void)out_size;

    cudaFuncSetAttribute(k_makeK, cudaFuncAttributeMaxDynamicSharedMemorySize, SMEMB);
    cudaFuncSetAttribute(k_conv,  cudaFuncAttributeMaxDynamicSharedMemorySize, SMEMB);

    k_cauchy<<<HCH, 256>>>(log_dt, w, Bm, Cm);      // also fills g_tw
    k_makeK<<<HCH, 512, SMEMB>>>(D);

    dim3 tb(8, 32);
    k_transpose_x<<<dim3(HCH/32, LEN/32, BSZ), tb>>>(x);
    k_conv<<<2048, 512, SMEMB>>>();
    k_transpose_y<<<dim3(LEN/32, HCH/32, BSZ), tb>>>(out);
}

// round 17
// speedup vs baseline: 1.4431x; 1.4431x over previous
#include <cuda_runtime.h>
#include <math.h>

#define HCH   512
#define NST   32
#define LEN   4096
#define M2    8192
#define BSZ   8
#define FCNT  2049
#define PI_D  3.14159265358979323846
#define C707  0.70710678118654752440f
#define CS16  0.92387953251128675613f
#define SN16  0.38268343236508977172f
#define SMEMN (M2 + M2/16)        /* 8704 float2 data region */
#define TWN   1024                /* smem twiddle table entries */
#define SMEMB ((SMEMN + TWN) * 8) /* 77824 bytes */

__device__ float2 g_kf[HCH * FCNT];
__device__ float2 g_KF[HCH * M2];        // scrambled order, transposed (r*512+t)
__device__ float  g_xT[BSZ * HCH * LEN];
__device__ float  g_yT[BSZ * HCH * LEN];
__device__ float2 g_tw[M2 / 2];          // exp(-2pi i k/8192)

__device__ __forceinline__ int P(int i) { return i + (i >> 4); }

union F2U { float2 f; unsigned long long u; };

__device__ __forceinline__ float2 cadd(float2 a, float2 b) {
    F2U ua, ub, uc; ua.f = a; ub.f = b;
    asm("add.rn.f32x2 %0, %1, %2;" : "=l"(uc.u) : "l"(ua.u), "l"(ub.u));
    return uc.f;
}
__device__ __forceinline__ float2 csub(float2 a, float2 b) {
    F2U ua, ub, uc; ua.f = a; ub.f = b;
    const unsigned long long NEG1 = 0xBF800000BF800000ULL;
    asm("fma.rn.f32x2 %0, %1, %2, %3;" : "=l"(uc.u)
        : "l"(ub.u), "l"(NEG1), "l"(ua.u));
    return uc.f;
}
__device__ __forceinline__ float2 cmulf(float2 a, float2 b) {
    return make_float2(a.x * b.x - a.y * b.y, a.x * b.y + a.y * b.x);
}

// forward 8-pt DIF network; slot r holds X[bitrev3(r)]
__device__ __forceinline__ void fft8f(float2 v[8]) {
    float2 a0=cadd(v[0],v[4]), a4=csub(v[0],v[4]);
    float2 a1=cadd(v[1],v[5]), a5=csub(v[1],v[5]);
    float2 a2=cadd(v[2],v[6]), a6=csub(v[2],v[6]);
    float2 a3=cadd(v[3],v[7]), a7=csub(v[3],v[7]);
    float2 t5 = make_float2(C707*(a5.x+a5.y),  C707*(a5.y-a5.x));   // *W8^1
    float2 t6 = make_float2(a6.y, -a6.x);                           // *W8^2
    float2 t7 = make_float2(C707*(a7.y-a7.x), -C707*(a7.x+a7.y));   // *W8^3
    float2 b0=cadd(a0,a2), b2=csub(a0,a2);
    float2 b1=cadd(a1,a3), b3=csub(a1,a3);
    float2 b4=cadd(a4,t6), b6=csub(a4,t6);
    float2 b5=cadd(t5,t7), b7=csub(t5,t7);
    float2 u3 = make_float2(b3.y, -b3.x);                           // *-i
    float2 u7 = make_float2(b7.y, -b7.x);
    v[0]=cadd(b0,b1); v[1]=csub(b0,b1);
    v[2]=cadd(b2,u3); v[3]=csub(b2,u3);
    v[4]=cadd(b4,b5); v[5]=csub(b4,b5);
    v[6]=cadd(b6,u7); v[7]=csub(b6,u7);
}

// exact mirror: input in fft8f slot order, output natural, unnormalized (x8)
__device__ __forceinline__ void ifft8(float2 v[8]) {
    float2 b0=cadd(v[0],v[1]), b1=csub(v[0],v[1]);
    float2 b2=cadd(v[2],v[3]), b3=csub(v[2],v[3]);
    float2 b4=cadd(v[4],v[5]), b5=csub(v[4],v[5]);
    float2 b6=cadd(v[6],v[7]), b7=csub(v[6],v[7]);
    b3 = make_float2(-b3.y, b3.x);   // *+i
    b7 = make_float2(-b7.y, b7.x);
    float2 a0=cadd(b0,b2), a2=csub(b0,b2);
    float2 a1=cadd(b1,b3), a3=csub(b1,b3);
    float2 a4=cadd(b4,b6), a6=csub(b4,b6);
    float2 a5=cadd(b5,b7), a7=csub(b5,b7);
    a5 = make_float2(C707*(a5.x-a5.y), C707*(a5.x+a5.y));   // *W8^-1
    a6 = make_float2(-a6.y, a6.x);                           // *+i
    a7 = make_float2(-C707*(a7.x+a7.y), C707*(a7.x-a7.y));  // *W8^-3
    v[0]=cadd(a0,a4); v[4]=csub(a0,a4);
    v[1]=cadd(a1,a5); v[5]=csub(a1,a5);
    v[2]=cadd(a2,a6); v[6]=csub(a2,a6);
    v[3]=cadd(a3,a7); v[7]=csub(a3,a7);
}

// 16-pt forward (DIT split even/odd); output slot s holds freq bitrev4(s)
__device__ __forceinline__ void fft16_fwd(float2 v[16]) {
    float2 g[8];
    #pragma unroll
    for (int r = 0; r < 8; r++) g[r] = v[2*r];
    fft8f(g);
    #pragma unroll
    for (int r = 0; r < 8; r++) v[2*r] = g[r];
    #pragma unroll
    for (int r = 0; r < 8; r++) g[r] = v[2*r+1];
    fft8f(g);
    { float2 x=g[1]; g[1]=make_float2( x.y, -x.x); }                              // W16^4
    { float2 x=g[2]; g[2]=make_float2(C707*(x.x+x.y),  C707*(x.y-x.x)); }         // W16^2
    { float2 x=g[3]; g[3]=make_float2(C707*(x.y-x.x), -C707*(x.x+x.y)); }         // W16^6
    { float2 x=g[4]; g[4]=make_float2(CS16*x.x+SN16*x.y,  CS16*x.y-SN16*x.x); }   // W16^1
    { float2 x=g[5]; g[5]=make_float2(CS16*x.y-SN16*x.x, -(CS16*x.x+SN16*x.y)); } // W16^5
    { float2 x=g[6]; g[6]=make_float2(SN16*x.x+CS16*x.y,  SN16*x.y-CS16*x.x); }   // W16^3
    { float2 x=g[7]; g[7]=make_float2(SN16*x.y-CS16*x.x, -(SN16*x.x+CS16*x.y)); } // W16^7
    #pragma unroll
    for (int r = 0; r < 8; r++) v[2*r+1] = g[r];
    #pragma unroll
    for (int r = 0; r < 8; r++) {
        float2 u = v[2*r], w = v[2*r+1];
        v[2*r] = cadd(u, w); v[2*r+1] = csub(u, w);
    }
}

// exact mirror of fft16_fwd, unnormalized (x16)
__device__ __forceinline__ void fft16_inv(float2 v[16]) {
    #pragma unroll
    for (int r = 0; r < 8; r++) {
        float2 u = v[2*r], w = v[2*r+1];
        v[2*r] = cadd(u, w); v[2*r+1] = csub(u, w);
    }
    float2 g[8];
    #pragma unroll
    for (int r = 0; r < 8; r++) g[r] = v[2*r];
    ifft8(g);
    #pragma unroll
    for (int r = 0; r < 8; r++) v[2*r] = g[r];
    #pragma unroll
    for (int r = 0; r < 8; r++) g[r] = v[2*r+1];
    { float2 x=g[1]; g[1]=make_float2(-x.y,  x.x); }
    { float2 x=g[2]; g[2]=make_float2(C707*(x.x-x.y),  C707*(x.x+x.y)); }
    { float2 x=g[3]; g[3]=make_float2(-C707*(x.x+x.y), C707*(x.x-x.y)); }
    { float2 x=g[4]; g[4]=make_float2(CS16*x.x-SN16*x.y,  CS16*x.y+SN16*x.x); }
    { float2 x=g[5]; g[5]=make_float2(-(SN16*x.x+CS16*x.y), CS16*x.x-SN16*x.y); }
    { float2 x=g[6]; g[6]=make_float2(SN16*x.x-CS16*x.y,  SN16*x.y+CS16*x.x); }
    { float2 x=g[7]; g[7]=make_float2(-(CS16*x.x+SN16*x.y), SN16*x.x-CS16*x.y); }
    ifft8(g);
    #pragma unroll
    for (int r = 0; r < 8; r++) v[2*r+1] = g[r];
}

// apply the 7 forward twiddles (slot order) given w1
__device__ __forceinline__ void twiddle_fwd(float2 v[8], float2 w1) {
    float2 w2 = cmulf(w1,w1), w3 = cmulf(w2,w1), w4 = cmulf(w2,w2);
    v[1]=cmulf(v[1],w4); v[2]=cmulf(v[2],w2); v[3]=cmulf(v[3],cmulf(w4,w2));
    v[4]=cmulf(v[4],w1); v[5]=cmulf(v[5],cmulf(w4,w1)); v[6]=cmulf(v[6],w3);
    v[7]=cmulf(v[7],cmulf(w4,w3));
}

// smem radix-8 DIF stage; NBF butterflies per thread (512 threads).
template<int L, int NBF>
__device__ __forceinline__ void stage8_dif(float2* a, const float2* tw) {
    const int half = L >> 3, tws = M2 / L, t = threadIdx.x;
    #pragma unroll
    for (int ii = 0; ii < NBF; ii++) {
        int i = t + ii * 512;
        int j = i & (half - 1);
        int p0 = ((i - j) << 3) + j;
        float2 v[8];
        #pragma unroll
        for (int r = 0; r < 8; r++) v[r] = a[P(p0 + r * half)];
        fft8f(v);
        twiddle_fwd(v, tw[j * tws]);
        #pragma unroll
        for (int r = 0; r < 8; r++) a[P(p0 + r * half)] = v[r];
    }
    __syncthreads();
}

// inverse mirror: conj twiddles first, then ifft8
template<int L, int NBF>
__device__ __forceinline__ void stage8_dit(float2* a, const float2* tw) {
    const int half = L >> 3, tws = M2 / L, t = threadIdx.x;
    #pragma unroll
    for (int ii = 0; ii < NBF; ii++) {
        int i = t + ii * 512;
        int j = i & (half - 1);
        int p0 = ((i - j) << 3) + j;
        float2 v[8];
        #pragma unroll
        for (int r = 0; r < 8; r++) v[r] = a[P(p0 + r * half)];
        float2 w1 = tw[j * tws]; w1.y = -w1.y;
        twiddle_fwd(v, w1);
        ifft8(v);
        #pragma unroll
        for (int r = 0; r < 8; r++) a[P(p0 + r * half)] = v[r];
    }
    __syncthreads();
}

// first 8192 DIF stage with upper half == 0, inputs from two real gmem series
__device__ __forceinline__ void stage1_fwd_gmem(float2* a, const float2* tw,
                                                const float* __restrict__ x0,
                                                const float* __restrict__ x1) {
    const int t = threadIdx.x;
    #pragma unroll
    for (int ii = 0; ii < 2; ii++) {
        int i = t + ii * 512;
        float2 v[8];
        #pragma unroll
        for (int r = 0; r < 4; r++) v[r] = make_float2(x0[i + r*1024], x1[i + r*1024]);
        #pragma unroll
        for (int r = 4; r < 8; r++) v[r] = make_float2(0.f, 0.f);
        fft8f(v);
        twiddle_fwd(v, tw[i]);
        #pragma unroll
        for (int r = 0; r < 8; r++) a[P(i + r * 1024)] = v[r];
    }
    __syncthreads();
}

// first 8192 DIF stage with upper half == 0, lower half already in smem (in place safe)
__device__ __forceinline__ void stage1_fwd_half(float2* a, const float2* tw) {
    const int t = threadIdx.x;
    #pragma unroll
    for (int ii = 0; ii < 2; ii++) {
        int i = t + ii * 512;
        float2 v[8];
        #pragma unroll
        for (int r = 0; r < 4; r++) v[r] = a[P(i + r*1024)];
        #pragma unroll
        for (int r = 4; r < 8; r++) v[r] = make_float2(0.f, 0.f);
        fft8f(v);
        twiddle_fwd(v, tw[i]);
        #pragma unroll
        for (int r = 0; r < 8; r++) a[P(i + r * 1024)] = v[r];
    }
    __syncthreads();
}

// last 8192 DIT stage fused with epilogue: only times < 4096 kept (D folded into K)
__device__ __forceinline__ void stageF_inv_gmem(float2* a, const float2* tw,
                                                float* __restrict__ y0,
                                                float* __restrict__ y1) {
    const int t = threadIdx.x;
    const float inv = 1.0f / (float)M2;
    #pragma unroll
    for (int ii = 0; ii < 2; ii++) {
        int i = t + ii * 512;
        float2 v[8];
        #pragma unroll
        for (int r = 0; r < 8; r++) v[r] = a[P(i + r * 1024)];
        float2 w1 = tw[i]; w1.y = -w1.y;
        twiddle_fwd(v, w1);
        ifft8(v);
        #pragma unroll
        for (int r = 0; r < 4; r++) {
            int p = i + r * 1024;
            y0[p] = v[r].x * inv;
            y1[p] = v[r].y * inv;
        }
    }
}

// middle of the 8192 transform (shared by fwd paths)
__device__ __forceinline__ void fwd8192_tail(float2* a, const float2* tw, float2 v[16]) {
    stage8_dif<1024,2>(a, tw);
    stage8_dif<128,2>(a, tw);
    const int t = threadIdx.x;
    #pragma unroll
    for (int r = 0; r < 16; r++) v[r] = a[P(16 * t + r)];
    fft16_fwd(v);
}

__device__ __forceinline__ void inv8192_head(float2* a, const float2* tw, float2 v[16]) {
    fft16_inv(v);
    const int t = threadIdx.x;
    #pragma unroll
    for (int r = 0; r < 16; r++) a[P(16 * t + r)] = v[r];
    __syncthreads();
    stage8_dit<128,2>(a, tw);
    stage8_dit<1024,2>(a, tw);
}

// Cauchy accumulation over modes; PAIRED halves divisions (unsafe only at f=2048)
template<bool PAIRED>
__device__ __forceinline__ void cauchy_acc(const float2 s_v[4][NST], const float2* s_wd,
                                           float zy, float2 r[4]) {
    #pragma unroll 8
    for (int n = 0; n < NST; n++) {
        float2 wd = s_wd[n];
        float dx = -wd.x, d1y = zy - wd.y, d2y = zy + wd.y;
        float A = dx*dx + d1y*d1y;
        float B = dx*dx + d2y*d2y;
        float m1, m2;
        if (PAIRED) {
            float invp = 1.0f / (A * B);
            m1 = invp * B; m2 = invp * A;
        } else {
            m1 = 1.0f / A; m2 = 1.0f / B;
        }
        float i1x = dx*m1, i1y = -d1y*m1;
        float i2x = dx*m2, i2y = -d2y*m2;
        float sx = i1x + i2x, dxy = i1y - i2y;
        float sy = i1y + i2y, dxx = i1x - i2x;
        float2 v;
        v = s_v[0][n]; r[0].x += v.x*sx - v.y*dxy; r[0].y += v.x*sy + v.y*dxx;
        v = s_v[1][n]; r[1].x += v.x*sx - v.y*dxy; r[1].y += v.x*sy + v.y*dxx;
        v = s_v[2][n]; r[2].x += v.x*sx - v.y*dxy; r[2].y += v.x*sy + v.y*dxx;
        v = s_v[3][n]; r[3].x += v.x*sx - v.y*dxy; r[3].y += v.x*sy + v.y*dxx;
    }
}

// Cauchy + Woodbury (also fills the global twiddle table — one fewer launch)
__global__ void k_cauchy(const float* __restrict__ log_dt,
                         const float2* __restrict__ w,
                         const float2* __restrict__ Bm,
                         const float2* __restrict__ Cm) {
    const int h = blockIdx.x, t = threadIdx.x;  // 256 thr
    int gid = h * 256 + t;
    if (gid < M2 / 2) {
        double sd, cd;
        sincos(-2.0 * PI_D * (double)gid / (double)M2, &sd, &cd);
        g_tw[gid] = make_float2((float)cd, (float)sd);
    }

    __shared__ float2 s_v[4][NST];
    __shared__ float2 s_wd[NST];
    __shared__ float s_dt;
    float dt = expf(log_dt[h]);
    if (t == 0) s_dt = dt;
    if (t < NST) { float2 ww = w[t]; s_wd[t] = make_float2(ww.x*dt, ww.y*dt); }
    if (t < 4 * NST) {
        int ab = t >> 5, n = t & 31, ai = ab >> 1, b = ab & 1;
        float2 C  = Cm[(h*2 + ai)*NST + n];
        float2 Bv = Bm[(h*2 + b)*NST + n];
        s_v[ab][n] = make_float2(C.x*Bv.x + C.y*Bv.y, C.x*Bv.y - C.y*Bv.x);
    }
    __syncthreads();
    dt = s_dt;
    const float piL = (float)(PI_D / LEN);
    for (int f = t; f < FCNT; f += blockDim.x) {
        float s;
        if (f == 0)          s = 0.0f;
        else if (f <= 1024)  s = tanf((float)f * piL);
        else if (f == 2048)  s = 1.633123935319537e16f;
        else                 s = 1.0f / tanf((float)(2048 - f) * piL);
        float zy = 2.0f * s;
        float2 r[4] = {make_float2(0,0), make_float2(0,0),
                       make_float2(0,0), make_float2(0,0)};
        if (f == 2048) cauchy_acc<false>(s_v, s_wd, zy, r);
        else           cauchy_acc<true >(s_v, s_wd, zy, r);
        #pragma unroll
        for (int k = 0; k < 4; k++) { r[k].x *= dt; r[k].y *= dt; }
        float2 den = make_float2(1.0f + r[3].x, r[3].y);
        float dm = 1.0f / (den.x*den.x + den.y*den.y);
        float2 num = cmulf(r[1], r[2]);
        float2 q = make_float2((num.x*den.x + num.y*den.y)*dm,
                               (num.y*den.x - num.x*den.y)*dm);
        float2 kf = make_float2(r[0].x - q.x, r[0].y - q.y);
        g_kf[h*FCNT + f] = make_float2(kf.x - kf.y*s, kf.y + kf.x*s);
    }
}

// makeK: ifft4096 via conj-forward (radix-8), scatter, half-zero first stage,
// forward 8192, fold D, store KF transposed in scrambled order.
__global__ __launch_bounds__(512, 2) void k_makeK(const float* __restrict__ D) {
    extern __shared__ float2 a[];
    float2* sw = a + SMEMN;
    const int h = blockIdx.x, t = threadIdx.x;

    for (int i = t; i < TWN; i += 512) sw[i] = g_tw[i];

    for (int f = t; f < FCNT; f += 512) {
        float2 vv = g_kf[h*FCNT + f];
        if (f == 0 || f == 2048) vv.y = 0.f;
        a[P(f)] = make_float2(vv.x, -vv.y);           // conj
        if (f > 0 && f < 2048) a[P(4096 - f)] = vv;
    }
    __syncthreads();

    stage8_dif<4096,1>(a, sw);
    stage8_dif<512,1>(a, sw);
    stage8_dif<64,1>(a, sw);
    float2 v8[8];
    #pragma unroll
    for (int r = 0; r < 8; r++) v8[r] = a[P(8*t + r)];
    fft8f(v8);
    __syncthreads();

    #pragma unroll
    for (int r = 0; r < 8; r++) {
        int p = 8*t + r;
        int m = __brev((unsigned)p) >> 20;   // bitrev12
        a[P(m)] = make_float2(v8[r].x * (1.0f / 4096.0f), 0.f);
    }
    __syncthreads();

    float2 v[16];
    stage1_fwd_half(a, sw);
    fwd8192_tail(a, sw, v);

    const float Dh = D[h];   // fold skip connection into the spectrum
    #pragma unroll
    for (int r = 0; r < 16; r++) v[r].x += Dh;
    #pragma unroll
    for (int r = 0; r < 16; r++) g_KF[h*M2 + (r << 9) + t] = v[r];  // transposed
}

__global__ void k_transpose_x(const float* __restrict__ x) {
    __shared__ float tile[32][33];
    const int b = blockIdx.z, h0 = blockIdx.x*32, t0 = blockIdx.y*32;
    const int tx = threadIdx.x, ty = threadIdx.y;
    #pragma unroll
    for (int k = 0; k < 4; k++)
        tile[ty + 8*k][tx] = x[(b*LEN + (t0 + ty + 8*k))*HCH + h0 + tx];
    __syncthreads();
    #pragma unroll
    for (int k = 0; k < 4; k++)
        g_xT[(b*HCH + (h0 + ty + 8*k))*LEN + t0 + tx] = tile[tx][ty + 8*k];
}

__global__ void k_transpose_y(float* __restrict__ out) {
    __shared__ float tile[32][33];
    const int b = blockIdx.z, t0 = blockIdx.x*32, h0 = blockIdx.y*32;
    const int tx = threadIdx.x, ty = threadIdx.y;
    #pragma unroll
    for (int k = 0; k < 4; k++)
        tile[ty + 8*k][tx] = g_yT[(b*HCH + (h0 + ty + 8*k))*LEN + t0 + tx];
    __syncthreads();
    #pragma unroll
    for (int k = 0; k < 4; k++)
        out[(b*LEN + (t0 + ty + 8*k))*HCH + h0 + tx] = tile[tx][ty + 8*k];
}

__global__ __launch_bounds__(512, 2) void k_conv() {
    extern __shared__ float2 a[];
    float2* sw = a + SMEMN;
    const int c = blockIdx.x, h = c & (HCH - 1), q = c >> 9, t = threadIdx.x;
    const float* x0 = g_xT + ((size_t)(2*q)*HCH + h)*LEN;
    const float* x1 = g_xT + ((size_t)(2*q + 1)*HCH + h)*LEN;

    for (int i = t; i < TWN; i += 512) sw[i] = g_tw[i];
    __syncthreads();

    float2 v[16];
    stage1_fwd_gmem(a, sw, x0, x1);
    fwd8192_tail(a, sw, v);

    const float2* KF = g_KF + (size_t)h * M2;
    #pragma unroll
    for (int r = 0; r < 16; r++) v[r] = cmulf(v[r], KF[(r << 9) + t]);

    inv8192_head(a, sw, v);
    stageF_inv_gmem(a, sw,
                    g_yT + ((size_t)(2*q)*HCH + h)*LEN,
                    g_yT + ((size_t)(2*q + 1)*HCH + h)*LEN);
}

extern "C" void kernel_launch(void* const* d_in, const int* in_sizes, int n_in,
                              void* d_out, int out_size) {
    const float*  x      = (const float*)d_in[0];
    const float*  log_dt = (const float*)d_in[1];
    const float2* w      = (const float2*)d_in[2];
    const float2* Bm     = (const float2*)d_in[3];
    const float2* Cm     = (const float2*)d_in[4];
    const float*  D      = (const float*)d_in[5];
    float* out = (float*)d_out;
    (void)in_sizes; (void)n_in; (void)out_size;

    cudaFuncSetAttribute(k_makeK, cudaFuncAttributeMaxDynamicSharedMemorySize, SMEMB);
    cudaFuncSetAttribute(k_conv,  cudaFuncAttributeMaxDynamicSharedMemorySize, SMEMB);

    k_cauchy<<<HCH, 256>>>(log_dt, w, Bm, Cm);      // also fills g_tw
    k_makeK<<<HCH, 512, SMEMB>>>(D);

    dim3 tb(32, 8);
    k_transpose_x<<<dim3(HCH/32, LEN/32, BSZ), tb>>>(x);
    k_conv<<<2048, 512, SMEMB>>>();
    k_transpose_y<<<dim3(LEN/32, HCH/32, BSZ), tb>>>(out);
}